// round 14
// baseline (speedup 1.0000x reference)
#include <cuda_runtime.h>
#include <cuda_bf16.h>
#include <math.h>

#define NTOT 4096
#define Q    1024
#define LDA  1024
#define NB   64
#define NBLK 128
#define NTHR 256

#define BAR192() asm volatile("bar.sync 1, 192;" ::: "memory")

// A is (Q+1) x Q: rows 0..1023 = S (trailing rows become TRSM'd L rows),
// row 1024 = border vector v (becomes w = L^-1 v)
__device__ __align__(128) float g_A[(Q + 1) * LDA];
__device__ float  g_u[Q];
__device__ int    g_cnt[Q];
__device__ double g_sumrr;
__device__ double g_uDu;
__device__ double g_logdet;
__device__ unsigned g_barGen = 0;
__device__ unsigned g_barCnt = 0;

__device__ __forceinline__ void grid_barrier() {
    __threadfence();
    __syncthreads();
    if (threadIdx.x == 0) {
        unsigned gen = *(volatile unsigned*)&g_barGen;
        if (atomicAdd(&g_barCnt, 1u) == NBLK - 1u) {
            g_barCnt = 0;
            __threadfence();
            *(volatile unsigned*)&g_barGen = gen + 1u;
        } else {
            while (*(volatile unsigned*)&g_barGen == gen) { __nanosleep(32); }
        }
    }
    __syncthreads();
    __threadfence();
}

// SYRK 64x64 tile (proven layout): rows r0.., cols c0.., K-panel at j0.
__device__ __forceinline__ void syrk_tile(int j0, int r0, int c0,
                                          float (*shA)[65], float (*shB)[65]) {
    const int tid = threadIdx.x;
    #pragma unroll 1
    for (int idx = tid; idx < 1024; idx += NTHR) {
        int rr = idx >> 4, c4 = (idx & 15) << 2;
        int gi = r0 + rr;
        float4 va = (gi <= Q) ? *(const float4*)&g_A[gi * LDA + j0 + c4]
                              : make_float4(0.f, 0.f, 0.f, 0.f);
        shA[rr][c4 + 0] = va.x; shA[rr][c4 + 1] = va.y;
        shA[rr][c4 + 2] = va.z; shA[rr][c4 + 3] = va.w;
        float4 vb = *(const float4*)&g_A[(c0 + rr) * LDA + j0 + c4];
        shB[rr][c4 + 0] = vb.x; shB[rr][c4 + 1] = vb.y;
        shB[rr][c4 + 2] = vb.z; shB[rr][c4 + 3] = vb.w;
    }
    __syncthreads();
    const int tx = tid & 15, ty = tid >> 4;
    float acc[4][4] = {};
    #pragma unroll
    for (int kk = 0; kk < 64; kk++) {
        float av[4], bv[4];
        #pragma unroll
        for (int qq = 0; qq < 4; qq++) {
            av[qq] = shA[(ty << 2) + qq][kk];
            bv[qq] = shB[(tx << 2) + qq][kk];
        }
        #pragma unroll
        for (int qa = 0; qa < 4; qa++)
            #pragma unroll
            for (int qb = 0; qb < 4; qb++)
                acc[qa][qb] += av[qa] * bv[qb];
    }
    #pragma unroll
    for (int qa = 0; qa < 4; qa++) {
        int i = r0 + (ty << 2) + qa;
        if (i <= Q) {
            float4* pp = (float4*)&g_A[i * LDA + c0 + (tx << 2)];
            float4 cur = *pp;
            cur.x -= acc[qa][0]; cur.y -= acc[qa][1];
            cur.z -= acc[qa][2]; cur.w -= acc[qa][3];
            *pp = cur;
        }
    }
    __syncthreads();
}

__global__ void __launch_bounds__(NTHR, 1)
mega_kernel(const float* __restrict__ yt,
            const float* __restrict__ yp,
            const int*   __restrict__ Z,
            const float* __restrict__ dist,
            const float* __restrict__ sig2e_p,
            const float* __restrict__ sig2bs,
            float* __restrict__ out)
{
    __shared__ __align__(16) float shA[64][65];
    __shared__ __align__(16) float shB[64][65];
    // rank-2 factor state (double-buffered by interval parity)
    __shared__ float colA_ev[2][32], colA_od[2][32];
    __shared__ float colB_ev[2][32], colB_od[2][32];
    __shared__ float shInvB[2], shDpre1[2], shSub[2];
    __shared__ float shD2[64], shDinv[64];
    __shared__ double shLg[2];
    __shared__ float  shRed[NTHR];
    __shared__ double shRedD[NTHR];

    const int bid  = blockIdx.x;
    const int tid  = threadIdx.x;
    const int lane = tid & 31;

    // ---------------- phase 0: init ----------------
    {
        int i = bid * NTHR + tid;
        if (i < Q) { g_u[i] = 0.f; g_cnt[i] = 0; }
        if (bid == 0 && tid == 0) { g_sumrr = 0.0; g_uDu = 0.0; g_logdet = 0.0; }
    }
    grid_barrier();

    // ---------------- phase 1: scatter (Z_idx arrives as int32) ----------------
    {
        int gi = bid * NTHR + tid;
        float r2 = 0.f;
        if (gi < NTOT) {
            float r = yt[gi] - yp[gi];
            int q = Z[gi] & (Q - 1);
            atomicAdd(&g_u[q], r);
            atomicAdd(&g_cnt[q], 1);
            r2 = r * r;
        }
        #pragma unroll
        for (int o = 16; o > 0; o >>= 1) r2 += __shfl_down_sync(0xffffffffu, r2, o);
        if (lane == 0 && (gi - lane) < NTOT) atomicAdd(&g_sumrr, (double)r2);
    }
    grid_barrier();

    // ---------------- phase 2: build S + border v + uDu (8 rows / block) -------
    {
        float s0   = sig2bs[0];
        float cexp = -0.5f / sig2bs[1];
        float se   = *sig2e_p;
        int4  c4 = *(const int4*)&g_cnt[tid * 4];
        float sw0 = sqrtf((float)c4.x), sw1 = sqrtf((float)c4.y);
        float sw2 = sqrtf((float)c4.z), sw3 = sqrtf((float)c4.w);
        float4 u4 = *(const float4*)&g_u[tid * 4];
        double uDu_loc = 0.0;
        float4 dv[8];
        #pragma unroll
        for (int ii = 0; ii < 8; ii++)
            dv[ii] = ((const float4*)(dist + (bid * 8 + ii) * Q))[tid];
        #pragma unroll
        for (int ii = 0; ii < 8; ii++) {
            int i = bid * 8 + ii;
            float swi = sqrtf((float)g_cnt[i]);
            float e0 = s0 * __expf(cexp * dv[ii].x);
            float e1 = s0 * __expf(cexp * dv[ii].y);
            float e2 = s0 * __expf(cexp * dv[ii].z);
            float e3 = s0 * __expf(cexp * dv[ii].w);
            float partial = e0 * u4.x + e1 * u4.y + e2 * u4.z + e3 * u4.w;
            float4 o;
            o.x = swi * sw0 * e0; o.y = swi * sw1 * e1;
            o.z = swi * sw2 * e2; o.w = swi * sw3 * e3;
            if ((i >> 2) == tid) {
                const int comp = ii & 3;
                if (comp == 0) o.x += se;
                else if (comp == 1) o.y += se;
                else if (comp == 2) o.z += se;
                else o.w += se;
            }
            ((float4*)&g_A[i * LDA])[tid] = o;
            shRed[tid] = partial;
            __syncthreads();
            for (int s = 128; s > 0; s >>= 1) {
                if (tid < s) shRed[tid] += shRed[tid + s];
                __syncthreads();
            }
            if (tid == 0) {
                float dot = shRed[0];
                g_A[Q * LDA + i] = swi * dot;      // border row v_i
                uDu_loc += (double)(g_u[i] * dot);
            }
            __syncthreads();
        }
        if (tid == 0) atomicAdd(&g_uDu, uDu_loc);
    }
    grid_barrier();

    // ---------------- phase 3: blocked bordered Cholesky, overlapped ----------
    for (int p = 0; p < Q / NB; p++) {
        const int j0 = p * NB;
        const int jb = j0 + NB;
        const int nrows = Q + 1 - jb;            // trailing rows incl. border
        const int nfb = (nrows + 31) >> 5;       // factor blocks (>=1)

        // ---- phase A: factor blocks run rank-2 factor + fused TRSM;
        //      idle blocks run leftover SYRK (cx>=1) of panel p-1 ----
        if (bid < nfb) {
            if (tid < 192) {
                const int par  = tid & 1;
                const int rIdx = tid >> 1;          // 0..63 diag, 64..95 trailing
                const bool isDiag = (tid < 128);
                int  myrow;
                bool valid;
                if (isDiag) { myrow = j0 + rIdx; valid = true; }
                else        { myrow = jb + bid * 32 + (rIdx - 64); valid = (myrow <= Q); }

                // a[kl] holds entry k = 2*kl + par of this row's 64-col slice
                float a[32];
                if (valid) {
                    const float4* src = (const float4*)&g_A[myrow * LDA + j0];
                    #pragma unroll
                    for (int t = 0; t < 16; t++) {
                        float4 v = src[t];
                        a[2*t]   = par ? v.y : v.x;
                        a[2*t+1] = par ? v.w : v.z;
                    }
                } else {
                    #pragma unroll
                    for (int t = 0; t < 32; t++) a[t] = 0.f;
                }

                // ---- pre-loop publishes: col 0 (B-slot), zeros (A-slot), scalars
                if (tid < 32)       colA_ev[0][tid]      = 0.f;
                else if (tid < 64)  colA_od[0][tid - 32] = 0.f;
                if (!par && isDiag) {
                    if (rIdx & 1) colB_od[0][rIdx >> 1] = a[0];
                    else          colB_ev[0][rIdx >> 1] = a[0];
                }
                if (tid == 0) { shD2[0] = a[0]; shInvB[0] = __fdividef(1.0f, a[0]); }
                if (tid == 3) shDpre1[0] = a[0];   // row1 diag initial (k=1,kl=0)
                if (tid == 5) shSub[0]   = a[0];   // a[2][1] initial (row2,k=1)
                float cB0 = a[0];
                float v0r = __shfl_xor_sync(0xffffffffu, cB0, 1);
                float cAown = 0.f;
                float cBown = par ? v0r : cB0;     // own row's col-0 value
                float invA_reg = 0.f;
                BAR192();

                // ---- main rank-2 chain: interval i publishes cols 2i+1, 2i+2
                #pragma unroll
                for (int i = 0; i < 31; i++) {
                    const int bufR = i & 1, bufW = bufR ^ 1;
                    float invB = shInvB[bufR];
                    float mA = cAown * invA_reg;
                    float mB = cBown * invB;
                    // redundant cross-row scalars (off the publish chain)
                    float cA1 = colA_od[bufR][i];       // col A at row c1=2i+1
                    float cB1 = colB_od[bufR][i];
                    float cA2 = colA_ev[bufR][i + 1];   // col A at row c2=2i+2
                    float cB2 = colB_ev[bufR][i + 1];
                    float d1 = shDpre1[bufR] - cA1 * cA1 * invA_reg - cB1 * cB1 * invB;
                    float invA_new = __fdividef(1.0f, d1);
                    float col1c2 = shSub[bufR] - (cA2 * invA_reg) * cA1 - (cB2 * invB) * cB1;
                    // fused dual-column tail (covers the new head entries too)
                    if (par) {
                        #pragma unroll
                        for (int kl = i; kl < 32; kl++)
                            a[kl] -= mA * colA_od[bufR][kl] + mB * colB_od[bufR][kl];
                    } else {
                        #pragma unroll
                        for (int kl = i + 1; kl < 32; kl++)
                            a[kl] -= mA * colA_ev[bufR][kl] + mB * colB_ev[bufR][kl];
                    }
                    // v1 = col c1 value (par1 rows)
                    float v1 = a[i];
                    if (par && isDiag) {
                        if (rIdx & 1) colA_od[bufW][rIdx >> 1] = v1;
                        else          colA_ev[bufW][rIdx >> 1] = v1;
                    }
                    if (tid == 4 * i + 3) shD2[2 * i + 1] = v1;   // diag row c1
                    float v1r = __shfl_xor_sync(0xffffffffu, v1, 1);
                    // v2 = col c2 value (par0 rows), rank-1 corrected by col c1
                    float v2 = 0.f;
                    if (!par) {
                        float m1 = v1r * invA_new;
                        v2 = a[i + 1] - m1 * col1c2;
                        a[i + 1] = v2;
                        if (isDiag) {
                            if (rIdx & 1) colB_od[bufW][rIdx >> 1] = v2;
                            else          colB_ev[bufW][rIdx >> 1] = v2;
                        }
                        if (tid == 4 * i + 4) {                    // diag row c2
                            shD2[2 * i + 2] = v2;
                            shInvB[bufW] = __fdividef(1.0f, v2);
                        }
                    }
                    float v2r = __shfl_xor_sync(0xffffffffu, v2, 1);
                    // register carries for next interval
                    cAown = par ? v1 : v1r;
                    cBown = par ? v2r : v2;
                    invA_reg = invA_new;
                    // scalars one interval ahead
                    if (tid == 4 * i + 7) shDpre1[bufW] = a[i + 1];  // row 2i+3 diag
                    if (i < 30 && tid == 4 * i + 9) shSub[bufW] = a[i + 1]; // a[2i+4][2i+3]
                    BAR192();
                }
                // ---- epilogue: col 63 gets cols 61 (A) and 62 (B) corrections
                {
                    float invB = shInvB[1];
                    float mA = cAown * invA_reg;
                    float mB = cBown * invB;
                    if (par) {
                        float v = a[31] - mA * colA_od[1][31] - mB * colB_od[1][31];
                        a[31] = v;
                        if (tid == 127) shD2[63] = v;   // diag row 63
                    }
                    BAR192();
                }

                if (tid < 64) shDinv[tid] = rsqrtf(shD2[tid]);
                BAR192();

                // trailing rows: scale by 1/d and store TRSM'd row
                if (!isDiag && valid) {
                    #pragma unroll
                    for (int t = 0; t < 32; t++)
                        g_A[myrow * LDA + j0 + 2 * t + par] = a[t] * shDinv[2 * t + par];
                }
                // logdet contribution (block 0 only)
                if (bid == 0) {
                    float lg = 0.f;
                    if (tid < 64) {
                        lg = 0.5f * logf(shD2[tid]);
                        #pragma unroll
                        for (int o = 16; o > 0; o >>= 1)
                            lg += __shfl_down_sync(0xffffffffu, lg, o);
                        if (tid == 0)  shLg[0] = (double)lg;
                        if (tid == 32) shLg[1] = (double)lg;
                    }
                    BAR192();
                    if (tid == 0) g_logdet += shLg[0] + shLg[1];
                }
            }
        } else if (p > 0) {
            // leftover SYRK of panel p-1: tile columns cx >= 1
            const int j0p = j0 - NB;
            const int jbp = j0;
            const int coltp = (Q - jbp) >> 6;
            const int rowtp = (Q + 1 - jbp + 63) >> 6;
            const int ntile = rowtp * coltp;
            const int nsb = NBLK - nfb;
            #pragma unroll 1
            for (int t = bid - nfb; t < ntile; t += nsb) {
                int ry = t / coltp, cx = t - ry * coltp;
                if (cx == 0 || cx > ry) continue;
                syrk_tile(j0p, jbp + ry * 64, jbp + cx * 64, shA, shB);
            }
        }
        grid_barrier();

        // ---- phase B: priority SYRK of panel p, tile column cx = 0 only ----
        {
            const int colt = (Q - jb) >> 6;
            if (colt > 0) {
                const int rowt = (nrows + 63) >> 6;
                #pragma unroll 1
                for (int t = bid; t < rowt; t += NBLK)
                    syrk_tile(j0, jb + t * 64, jb, shA, shB);
            }
        }
        grid_barrier();
    }

    // ---------------- phase 4: final reduction (block 0) ----------------
    if (bid == 0) {
        double t = 0.0;
        for (int j = tid; j < Q; j += NTHR) {
            float w = g_A[Q * LDA + j];
            t += (double)w * (double)w;
        }
        shRedD[tid] = t;
        __syncthreads();
        for (int s = 128; s > 0; s >>= 1) {
            if (tid < s) shRedD[tid] += shRedD[tid + s];
            __syncthreads();
        }
        if (tid == 0) {
            double tt  = shRedD[0];
            double se  = (double)(*sig2e_p);
            double inv = 1.0 / se;
            double quad    = inv * g_sumrr - inv * inv * (g_uDu - tt);
            double logdetV = ((double)NTOT - (double)Q) * log(se) + 2.0 * g_logdet;
            const double LOG2PI = 1.8378770664093454835606594728112;
            out[0] = (float)(0.5 * (double)NTOT * LOG2PI + 0.5 * logdetV + 0.5 * quad);
        }
    }
}

extern "C" void kernel_launch(void* const* d_in, const int* in_sizes, int n_in,
                              void* d_out, int out_size) {
    const float* y_true = (const float*)d_in[0];
    const float* y_pred = (const float*)d_in[1];
    const int*   Z_idx  = (const int*)d_in[2];
    const float* dist   = (const float*)d_in[3];
    const float* sig2e  = (const float*)d_in[4];
    const float* sig2bs = (const float*)d_in[5];
    float* out = (float*)d_out;

    mega_kernel<<<NBLK, NTHR>>>(y_true, y_pred, Z_idx, dist, sig2e, sig2bs, out);
}

// round 15
// speedup vs baseline: 1.4317x; 1.4317x over previous
#include <cuda_runtime.h>
#include <cuda_bf16.h>
#include <math.h>

#define NTOT 4096
#define Q    1024
#define LDA  1024
#define NB   64
#define NBLK 128
#define NTHR 256

#define BAR192() asm volatile("bar.sync 1, 192;" ::: "memory")

// A is (Q+1) x Q: rows 0..1023 = S (trailing rows become TRSM'd L rows),
// row 1024 = border vector v (becomes w = L^-1 v)
__device__ __align__(128) float g_A[(Q + 1) * LDA];
__device__ float  g_u[Q];
__device__ int    g_cnt[Q];
__device__ double g_sumrr;
__device__ double g_uDu;
__device__ double g_logdet;
__device__ unsigned g_barGen = 0;
__device__ unsigned g_barCnt = 0;

__device__ __forceinline__ void grid_barrier() {
    __threadfence();
    __syncthreads();
    if (threadIdx.x == 0) {
        unsigned gen = *(volatile unsigned*)&g_barGen;
        if (atomicAdd(&g_barCnt, 1u) == NBLK - 1u) {
            g_barCnt = 0;
            __threadfence();
            *(volatile unsigned*)&g_barGen = gen + 1u;
        } else {
            while (*(volatile unsigned*)&g_barGen == gen) { __nanosleep(32); }
        }
    }
    __syncthreads();
    __threadfence();
}

// SYRK 64x64 tile (proven layout): rows r0.., cols c0.., K-panel at j0.
__device__ __forceinline__ void syrk_tile(int j0, int r0, int c0,
                                          float (*shA)[65], float (*shB)[65]) {
    const int tid = threadIdx.x;
    #pragma unroll 1
    for (int idx = tid; idx < 1024; idx += NTHR) {
        int rr = idx >> 4, c4 = (idx & 15) << 2;
        int gi = r0 + rr;
        float4 va = (gi <= Q) ? *(const float4*)&g_A[gi * LDA + j0 + c4]
                              : make_float4(0.f, 0.f, 0.f, 0.f);
        shA[rr][c4 + 0] = va.x; shA[rr][c4 + 1] = va.y;
        shA[rr][c4 + 2] = va.z; shA[rr][c4 + 3] = va.w;
        float4 vb = *(const float4*)&g_A[(c0 + rr) * LDA + j0 + c4];
        shB[rr][c4 + 0] = vb.x; shB[rr][c4 + 1] = vb.y;
        shB[rr][c4 + 2] = vb.z; shB[rr][c4 + 3] = vb.w;
    }
    __syncthreads();
    const int tx = tid & 15, ty = tid >> 4;
    float acc[4][4] = {};
    #pragma unroll
    for (int kk = 0; kk < 64; kk++) {
        float av[4], bv[4];
        #pragma unroll
        for (int qq = 0; qq < 4; qq++) {
            av[qq] = shA[(ty << 2) + qq][kk];
            bv[qq] = shB[(tx << 2) + qq][kk];
        }
        #pragma unroll
        for (int qa = 0; qa < 4; qa++)
            #pragma unroll
            for (int qb = 0; qb < 4; qb++)
                acc[qa][qb] += av[qa] * bv[qb];
    }
    #pragma unroll
    for (int qa = 0; qa < 4; qa++) {
        int i = r0 + (ty << 2) + qa;
        if (i <= Q) {
            float4* pp = (float4*)&g_A[i * LDA + c0 + (tx << 2)];
            float4 cur = *pp;
            cur.x -= acc[qa][0]; cur.y -= acc[qa][1];
            cur.z -= acc[qa][2]; cur.w -= acc[qa][3];
            *pp = cur;
        }
    }
    __syncthreads();
}

__global__ void __launch_bounds__(NTHR, 1)
mega_kernel(const float* __restrict__ yt,
            const float* __restrict__ yp,
            const int*   __restrict__ Z,
            const float* __restrict__ dist,
            const float* __restrict__ sig2e_p,
            const float* __restrict__ sig2bs,
            float* __restrict__ out)
{
    __shared__ __align__(16) float shA[64][65];
    __shared__ __align__(16) float shB[64][65];
    __shared__ float  shcol[2][96];
    __shared__ float  shInv[2];
    __shared__ float  shD2[64];
    __shared__ float  shDinv[64];
    __shared__ double shLg[2];
    __shared__ float  shRed[NTHR];
    __shared__ double shRedD[NTHR];

    const int bid  = blockIdx.x;
    const int tid  = threadIdx.x;
    const int lane = tid & 31;

    // ---------------- phase 0: init ----------------
    {
        int i = bid * NTHR + tid;
        if (i < Q) { g_u[i] = 0.f; g_cnt[i] = 0; }
        if (bid == 0 && tid == 0) { g_sumrr = 0.0; g_uDu = 0.0; g_logdet = 0.0; }
    }
    grid_barrier();

    // ---------------- phase 1: scatter (Z_idx arrives as int32) ----------------
    {
        int gi = bid * NTHR + tid;
        float r2 = 0.f;
        if (gi < NTOT) {
            float r = yt[gi] - yp[gi];
            int q = Z[gi] & (Q - 1);
            atomicAdd(&g_u[q], r);
            atomicAdd(&g_cnt[q], 1);
            r2 = r * r;
        }
        #pragma unroll
        for (int o = 16; o > 0; o >>= 1) r2 += __shfl_down_sync(0xffffffffu, r2, o);
        if (lane == 0 && (gi - lane) < NTOT) atomicAdd(&g_sumrr, (double)r2);
    }
    grid_barrier();

    // ---------------- phase 2: build S + border v + uDu (8 rows / block) -------
    {
        float s0   = sig2bs[0];
        float cexp = -0.5f / sig2bs[1];
        float se   = *sig2e_p;
        int4  c4 = *(const int4*)&g_cnt[tid * 4];
        float sw0 = sqrtf((float)c4.x), sw1 = sqrtf((float)c4.y);
        float sw2 = sqrtf((float)c4.z), sw3 = sqrtf((float)c4.w);
        float4 u4 = *(const float4*)&g_u[tid * 4];
        double uDu_loc = 0.0;
        float4 dv[8];
        #pragma unroll
        for (int ii = 0; ii < 8; ii++)
            dv[ii] = ((const float4*)(dist + (bid * 8 + ii) * Q))[tid];
        #pragma unroll
        for (int ii = 0; ii < 8; ii++) {
            int i = bid * 8 + ii;
            float swi = sqrtf((float)g_cnt[i]);
            float e0 = s0 * __expf(cexp * dv[ii].x);
            float e1 = s0 * __expf(cexp * dv[ii].y);
            float e2 = s0 * __expf(cexp * dv[ii].z);
            float e3 = s0 * __expf(cexp * dv[ii].w);
            float partial = e0 * u4.x + e1 * u4.y + e2 * u4.z + e3 * u4.w;
            float4 o;
            o.x = swi * sw0 * e0; o.y = swi * sw1 * e1;
            o.z = swi * sw2 * e2; o.w = swi * sw3 * e3;
            if ((i >> 2) == tid) {
                const int comp = ii & 3;
                if (comp == 0) o.x += se;
                else if (comp == 1) o.y += se;
                else if (comp == 2) o.z += se;
                else o.w += se;
            }
            ((float4*)&g_A[i * LDA])[tid] = o;
            shRed[tid] = partial;
            __syncthreads();
            for (int s = 128; s > 0; s >>= 1) {
                if (tid < s) shRed[tid] += shRed[tid + s];
                __syncthreads();
            }
            if (tid == 0) {
                float dot = shRed[0];
                g_A[Q * LDA + i] = swi * dot;      // border row v_i
                uDu_loc += (double)(g_u[i] * dot);
            }
            __syncthreads();
        }
        if (tid == 0) atomicAdd(&g_uDu, uDu_loc);
    }
    grid_barrier();

    // ---------------- phase 3: blocked bordered Cholesky, overlapped ----------
    for (int p = 0; p < Q / NB; p++) {
        const int j0 = p * NB;
        const int jb = j0 + NB;
        const int nrows = Q + 1 - jb;            // trailing rows incl. border
        const int nfb = (nrows + 31) >> 5;       // factor blocks (>=1)

        // ---- phase A: factor blocks run half-split factor + fused TRSM;
        //      idle blocks run leftover SYRK (cx>=1) of panel p-1 ----
        if (bid < nfb) {
            if (tid < 192) {
                // warp-segregated halves:
                //  tid   0..63 : diag rows 0..63,  cols [0,32)   (half 0)
                //  tid  64..127: diag rows 0..63,  cols [32,64)  (half 1)
                //  tid 128..159: trailing rows 0..31, cols [0,32)  (half 0)
                //  tid 160..191: trailing rows 0..31, cols [32,64) (half 1)
                const bool isDiag = (tid < 128);
                int myHalf, myIdx, myrow;
                bool valid;
                if (isDiag) {
                    myHalf = (tid >= 64);
                    myIdx  = tid & 63;                 // diag row
                    myrow  = j0 + myIdx;
                    valid  = true;
                } else {
                    myHalf = (tid >= 160);
                    int trow = (tid - 128) & 31;       // trailing slot
                    myIdx  = 64 + trow;
                    myrow  = jb + bid * 32 + trow;
                    valid  = (myrow <= Q);
                }
                const int base = myHalf << 5;          // 0 or 32

                float a[32];                           // cols [base, base+32)
                if (valid) {
                    const float4* src = (const float4*)&g_A[myrow * LDA + j0 + base];
                    #pragma unroll
                    for (int t = 0; t < 8; t++) {
                        float4 v = src[t];
                        a[4*t] = v.x; a[4*t+1] = v.y; a[4*t+2] = v.z; a[4*t+3] = v.w;
                    }
                } else {
                    #pragma unroll
                    for (int t = 0; t < 32; t++) a[t] = 0.f;
                }

                // pre-loop: publish column 0 (owned by half 0), scalars
                if (myHalf == 0) shcol[0][myIdx] = a[0];
                if (tid == 0) { shD2[0] = a[0]; shInv[0] = __fdividef(1.0f, a[0]); }
                BAR192();

                #pragma unroll
                for (int j = 0; j < 63; j++) {
                    const int cb = j & 1, nb2 = cb ^ 1;
                    const int hstar = (j + 1) >> 5;    // compile-time
                    const int klh   = (j + 1) & 31;
                    float m = shcol[cb][myIdx] * shInv[cb];
                    // head: entry j+1 (owned by warp-group hstar) -> publish
                    if (myHalf == hstar) {
                        float v = a[klh] - m * shcol[cb][j + 1];
                        a[klh] = v;
                        shcol[nb2][myIdx] = v;
                        if (tid == hstar * 64 + (j + 1)) {   // diag row j+1 owner
                            shD2[j + 1] = v;
                            shInv[nb2] = __fdividef(1.0f, v);
                        }
                    }
                    // tail: entries k >= j+2, compile-time bounds per half
                    if (myHalf == 0) {
                        #pragma unroll
                        for (int kl = j + 2; kl < 32; kl++)
                            a[kl] -= m * shcol[cb][kl];
                    } else {
                        #pragma unroll
                        for (int kl = (j - 30 > 0 ? j - 30 : 0); kl < 32; kl++)
                            a[kl] -= m * shcol[cb][32 + kl];
                    }
                    BAR192();
                }

                if (tid < 64) shDinv[tid] = rsqrtf(shD2[tid]);
                BAR192();

                // trailing rows: scale by 1/d, store TRSM'd half (contiguous)
                if (!isDiag && valid) {
                    float4* dst = (float4*)&g_A[myrow * LDA + j0 + base];
                    #pragma unroll
                    for (int t = 0; t < 8; t++) {
                        float4 v;
                        v.x = a[4*t]   * shDinv[base + 4*t];
                        v.y = a[4*t+1] * shDinv[base + 4*t+1];
                        v.z = a[4*t+2] * shDinv[base + 4*t+2];
                        v.w = a[4*t+3] * shDinv[base + 4*t+3];
                        dst[t] = v;
                    }
                }
                // logdet contribution (block 0 only)
                if (bid == 0) {
                    float lg = 0.f;
                    if (tid < 64) {
                        lg = 0.5f * logf(shD2[tid]);
                        #pragma unroll
                        for (int o = 16; o > 0; o >>= 1)
                            lg += __shfl_down_sync(0xffffffffu, lg, o);
                        if (tid == 0)  shLg[0] = (double)lg;
                        if (tid == 32) shLg[1] = (double)lg;
                    }
                    BAR192();
                    if (tid == 0) g_logdet += shLg[0] + shLg[1];
                }
            }
        } else if (p > 0) {
            // leftover SYRK of panel p-1: tile columns cx >= 1
            const int j0p = j0 - NB;
            const int jbp = j0;
            const int coltp = (Q - jbp) >> 6;
            const int rowtp = (Q + 1 - jbp + 63) >> 6;
            const int ntile = rowtp * coltp;
            const int nsb = NBLK - nfb;
            #pragma unroll 1
            for (int t = bid - nfb; t < ntile; t += nsb) {
                int ry = t / coltp, cx = t - ry * coltp;
                if (cx == 0 || cx > ry) continue;
                syrk_tile(j0p, jbp + ry * 64, jbp + cx * 64, shA, shB);
            }
        }
        grid_barrier();

        // ---- phase B: priority SYRK of panel p, tile column cx = 0 only ----
        {
            const int colt = (Q - jb) >> 6;
            if (colt > 0) {
                const int rowt = (nrows + 63) >> 6;
                #pragma unroll 1
                for (int t = bid; t < rowt; t += NBLK)
                    syrk_tile(j0, jb + t * 64, jb, shA, shB);
            }
        }
        grid_barrier();
    }

    // ---------------- phase 4: final reduction (block 0) ----------------
    if (bid == 0) {
        double t = 0.0;
        for (int j = tid; j < Q; j += NTHR) {
            float w = g_A[Q * LDA + j];
            t += (double)w * (double)w;
        }
        shRedD[tid] = t;
        __syncthreads();
        for (int s = 128; s > 0; s >>= 1) {
            if (tid < s) shRedD[tid] += shRedD[tid + s];
            __syncthreads();
        }
        if (tid == 0) {
            double tt  = shRedD[0];
            double se  = (double)(*sig2e_p);
            double inv = 1.0 / se;
            double quad    = inv * g_sumrr - inv * inv * (g_uDu - tt);
            double logdetV = ((double)NTOT - (double)Q) * log(se) + 2.0 * g_logdet;
            const double LOG2PI = 1.8378770664093454835606594728112;
            out[0] = (float)(0.5 * (double)NTOT * LOG2PI + 0.5 * logdetV + 0.5 * quad);
        }
    }
}

extern "C" void kernel_launch(void* const* d_in, const int* in_sizes, int n_in,
                              void* d_out, int out_size) {
    const float* y_true = (const float*)d_in[0];
    const float* y_pred = (const float*)d_in[1];
    const int*   Z_idx  = (const int*)d_in[2];
    const float* dist   = (const float*)d_in[3];
    const float* sig2e  = (const float*)d_in[4];
    const float* sig2bs = (const float*)d_in[5];
    float* out = (float*)d_out;

    mega_kernel<<<NBLK, NTHR>>>(y_true, y_pred, Z_idx, dist, sig2e, sig2bs, out);
}